// round 7
// baseline (speedup 1.0000x reference)
#include <cuda_runtime.h>
#include <cuda_bf16.h>
#include <cstdint>

// LayerNorm over last dim W=256 for (8,128,128,256) fp32 + per-channel affine.
// R6 base (1 warp/row, coalesced 2x LDG.128, plain loads/stores) plus:
//  - (s,ss) packed into f32x2 for the warp reduce: 2 SHFL + 1 packed ADD per
//    level instead of 2 SHFL + 2 FADD -> shorter serial tail.
//  - block = 128 (4 warps): finer CTA retire granularity / wave packing.

#define EPS 1e-8f
#define W_DIM 256
#define C_DIM 128

__global__ __launch_bounds__(128, 16)
void ln_coal2_kernel(const float* __restrict__ inp,
                     const float* __restrict__ gain,
                     const float* __restrict__ bias,
                     float* __restrict__ out,
                     int n_rows)
{
    const int warp_in_block = threadIdx.x >> 5;
    const int lane = threadIdx.x & 31;
    const int row = blockIdx.x * 4 + warp_in_block;
    if (row >= n_rows) return;

    // Affine params (independent; overlap bulk-load latency).
    const int c = (row >> 7) & (C_DIM - 1);   // row = ((b*C+c)*H + h), H=128
    const float g = __ldg(gain + c);
    const float b = __ldg(bias + c);

    const float4* in4 = reinterpret_cast<const float4*>(inp) + (size_t)row * 64;
    float4*      out4 = reinterpret_cast<float4*>(out)       + (size_t)row * 64;

    // Fully coalesced: each LDG.128 covers a contiguous 512B.
    float4 v0 = in4[lane];
    float4 v1 = in4[lane + 32];

    float s  = ((v0.x + v0.y) + (v0.z + v0.w)) + ((v1.x + v1.y) + (v1.z + v1.w));
    float ss = ((v0.x*v0.x + v0.y*v0.y) + (v0.z*v0.z + v0.w*v0.w))
             + ((v1.x*v1.x + v1.y*v1.y) + (v1.z*v1.z + v1.w*v1.w));

    // Packed (s,ss) warp reduce: shuffle both halves, one f32x2 add per level.
    uint64_t pair;
    asm("mov.b64 %0, {%1, %2};" : "=l"(pair) : "f"(s), "f"(ss));
    #pragma unroll
    for (int off = 16; off > 0; off >>= 1) {
        uint32_t lo, hi;
        asm("mov.b64 {%0, %1}, %2;" : "=r"(lo), "=r"(hi) : "l"(pair));
        lo = __shfl_xor_sync(0xFFFFFFFFu, lo, off);
        hi = __shfl_xor_sync(0xFFFFFFFFu, hi, off);
        uint64_t other;
        asm("mov.b64 %0, {%1, %2};" : "=l"(other) : "r"(lo), "r"(hi));
        asm("add.rn.f32x2 %0, %1, %2;" : "=l"(pair) : "l"(pair), "l"(other));
    }
    asm("mov.b64 {%0, %1}, %2;" : "=f"(s), "=f"(ss) : "l"(pair));

    const float inv_w = 1.0f / (float)W_DIM;
    float mean = s * inv_w;
    float var  = ss * inv_w - mean * mean;
    float rstd = rsqrtf(var + EPS);

    float scale = rstd * g;
    float shift = b - mean * scale;

    v0.x = v0.x * scale + shift;  v0.y = v0.y * scale + shift;
    v0.z = v0.z * scale + shift;  v0.w = v0.w * scale + shift;
    v1.x = v1.x * scale + shift;  v1.y = v1.y * scale + shift;
    v1.z = v1.z * scale + shift;  v1.w = v1.w * scale + shift;

    out4[lane]      = v0;
    out4[lane + 32] = v1;
}

extern "C" void kernel_launch(void* const* d_in, const int* in_sizes, int n_in,
                              void* d_out, int out_size) {
    const float* inp  = (const float*)d_in[0];
    const float* gain = (const float*)d_in[1];
    const float* bias = (const float*)d_in[2];
    float* out = (float*)d_out;

    int n_rows = in_sizes[0] / W_DIM;   // 131072
    int blocks = (n_rows + 3) / 4;      // 32768, 4 warps (rows) per block

    ln_coal2_kernel<<<blocks, 128>>>(inp, gain, bias, out, n_rows);
}

// round 8
// speedup vs baseline: 1.0265x; 1.0265x over previous
#include <cuda_runtime.h>
#include <cuda_bf16.h>
#include <cstdint>

// LayerNorm over last dim W=256 for (8,128,128,256) fp32 + per-channel affine.
// Recombination of the two measured-best variants:
//  - R6 launch shape: 256 threads/block, 16384 blocks (best timed result)
//  - R7 packed (s,ss) f32x2 warp reduce (best kernel-interior time)
//  - coalesced lane layout (in4[lane], in4[lane+32]), plain LDG/STG.

#define EPS 1e-8f
#define W_DIM 256
#define C_DIM 128

__global__ __launch_bounds__(256, 8)
void ln_final_kernel(const float* __restrict__ inp,
                     const float* __restrict__ gain,
                     const float* __restrict__ bias,
                     float* __restrict__ out,
                     int n_rows)
{
    const int warp_in_block = threadIdx.x >> 5;
    const int lane = threadIdx.x & 31;
    const int row = blockIdx.x * 8 + warp_in_block;
    if (row >= n_rows) return;

    // Affine params (independent loads; overlap bulk-load latency).
    const int c = (row >> 7) & (C_DIM - 1);   // row = ((b*C+c)*H + h), H=128
    const float g = __ldg(gain + c);
    const float b = __ldg(bias + c);

    const float4* in4 = reinterpret_cast<const float4*>(inp) + (size_t)row * 64;
    float4*      out4 = reinterpret_cast<float4*>(out)       + (size_t)row * 64;

    // Fully coalesced: each LDG.128 covers a contiguous 512B of the row.
    float4 v0 = in4[lane];
    float4 v1 = in4[lane + 32];

    float s  = ((v0.x + v0.y) + (v0.z + v0.w)) + ((v1.x + v1.y) + (v1.z + v1.w));
    float ss = ((v0.x*v0.x + v0.y*v0.y) + (v0.z*v0.z + v0.w*v0.w))
             + ((v1.x*v1.x + v1.y*v1.y) + (v1.z*v1.z + v1.w*v1.w));

    // Packed (s,ss) warp reduce: 2 SHFL + 1 add.rn.f32x2 per level.
    uint64_t pair;
    asm("mov.b64 %0, {%1, %2};" : "=l"(pair) : "f"(s), "f"(ss));
    #pragma unroll
    for (int off = 16; off > 0; off >>= 1) {
        uint32_t lo, hi;
        asm("mov.b64 {%0, %1}, %2;" : "=r"(lo), "=r"(hi) : "l"(pair));
        lo = __shfl_xor_sync(0xFFFFFFFFu, lo, off);
        hi = __shfl_xor_sync(0xFFFFFFFFu, hi, off);
        uint64_t other;
        asm("mov.b64 %0, {%1, %2};" : "=l"(other) : "r"(lo), "r"(hi));
        asm("add.rn.f32x2 %0, %1, %2;" : "=l"(pair) : "l"(pair), "l"(other));
    }
    asm("mov.b64 {%0, %1}, %2;" : "=f"(s), "=f"(ss) : "l"(pair));

    const float inv_w = 1.0f / (float)W_DIM;
    float mean = s * inv_w;
    float var  = ss * inv_w - mean * mean;
    float rstd = rsqrtf(var + EPS);

    float scale = rstd * g;
    float shift = b - mean * scale;

    v0.x = v0.x * scale + shift;  v0.y = v0.y * scale + shift;
    v0.z = v0.z * scale + shift;  v0.w = v0.w * scale + shift;
    v1.x = v1.x * scale + shift;  v1.y = v1.y * scale + shift;
    v1.z = v1.z * scale + shift;  v1.w = v1.w * scale + shift;

    out4[lane]      = v0;
    out4[lane + 32] = v1;
}

extern "C" void kernel_launch(void* const* d_in, const int* in_sizes, int n_in,
                              void* d_out, int out_size) {
    const float* inp  = (const float*)d_in[0];
    const float* gain = (const float*)d_in[1];
    const float* bias = (const float*)d_in[2];
    float* out = (float*)d_out;

    int n_rows = in_sizes[0] / W_DIM;   // 131072
    int blocks = (n_rows + 7) / 8;      // 16384, 8 warps (rows) per block

    ln_final_kernel<<<blocks, 256>>>(inp, gain, bias, out, n_rows);
}